// round 12
// baseline (speedup 1.0000x reference)
#include <cuda_runtime.h>
#include <cstdint>

// Problem constants (fixed by setup_inputs)
#define B_      16
#define T_      1024
#define D_      384
#define MAXDUR_ 4
#define OUTLEN_ (T_ * MAXDUR_)      // 4096
#define D4_     (D_ / 4)            // 96 float4 per row

#define NTHREADS     384
#define CTAS_PER_B   128            // src rows per CTA = 1024/128 = 8
#define SRC_PER_CTA  8              // each CTA expands 8 source rows
#define PAD_PER_CTA  32             // each CTA pad-checks 32 output rows

// ---------------------------------------------------------------------------
// Fused kernel (single launch): per-CTA duration scan (redundant per batch,
// 4 KB int4 load, L2-broadcast) + source-major expand (each xs row read ONCE,
// written to its d destinations) + pad fill for rows >= total.
// All output stores are __stcs: measured +6us harness penalty for letting
// 100MB of dirty lines squat in L2 across graph replays (R8 vs R2).
// Grid: 2048 CTAs (128 per batch), 384 threads.
// ---------------------------------------------------------------------------
__global__ void __launch_bounds__(NTHREADS) lr_fused_kernel(
    const float4* __restrict__ xs, const int* __restrict__ ds,
    float4* __restrict__ out) {

    __shared__ int sm_ds[T_];        // durations for this batch
    __shared__ int sm_excl[T_ / 4];  // exclusive cumsum per int4 group
    __shared__ int sm_wsum[8];
    __shared__ int sm_total;

    const int bid  = blockIdx.x;
    const int b    = bid >> 7;            // batch
    const int cb   = bid & (CTAS_PER_B - 1);
    const int tid  = threadIdx.x;
    const int col  = tid % D4_;           // 0..95
    const int slot = tid / D4_;           // 0..3

    const int r0 = cb * SRC_PER_CTA;      // first src row of this CTA
    const float4* __restrict__ xb = xs + (size_t)b * T_ * D4_;
    float4* __restrict__ ob = out + (size_t)b * OUTLEN_ * D4_;

    // -------- issue the 2 xs row loads immediately (address is static) ------
    const int ra = r0 + slot;             // src row, k=0
    const int rb = r0 + 4 + slot;         // src row, k=1
    float4 va = __ldg(&xb[(size_t)ra * D4_ + col]);
    float4 vb = __ldg(&xb[(size_t)rb * D4_ + col]);

    // -------- per-CTA scan of this batch's 1024 durations -------------------
    const int lane = tid & 31;
    int x = 0, p = 0;
    if (tid < 256) {
        int4 v = __ldg(&((const int4*)(ds + b * T_))[tid]);
        ((int4*)sm_ds)[tid] = v;
        p = v.x + v.y + v.z + v.w;
        x = p;
        #pragma unroll
        for (int off = 1; off < 32; off <<= 1) {
            int y = __shfl_up_sync(0xffffffffu, x, off);
            if (lane >= off) x += y;
        }
        if (lane == 31) sm_wsum[tid >> 5] = x;
    }
    __syncthreads();
    if (tid == 0) {
        int run = 0;
        #pragma unroll
        for (int w = 0; w < 8; w++) { int t = sm_wsum[w]; sm_wsum[w] = run; run += t; }
        sm_total = run;
    }
    __syncthreads();
    if (tid < 256) sm_excl[tid] = sm_wsum[tid >> 5] + (x - p);
    __syncthreads();

    const int total = sm_total;

    // -------- expand: write each src row to its [start, start+d) slots ------
    {
        const int ga = ra >> 2;
        int sta = sm_excl[ga];
        for (int j = ga << 2; j < ra; j++) sta += sm_ds[j];
        const int da = sm_ds[ra];

        const int gb = rb >> 2;
        int stb = sm_excl[gb];
        for (int j = gb << 2; j < rb; j++) stb += sm_ds[j];
        const int db = sm_ds[rb];

        for (int j = 0; j < da; j++)
            __stcs(&ob[(size_t)(sta + j) * D4_ + col], va);
        for (int j = 0; j < db; j++)
            __stcs(&ob[(size_t)(stb + j) * D4_ + col], vb);
    }

    // -------- pad fill: zero output rows [total, 4096) in our slice ---------
    {
        const float4 z = make_float4(0.f, 0.f, 0.f, 0.f);
        const int o0 = cb * PAD_PER_CTA;
        #pragma unroll
        for (int k = 0; k < PAD_PER_CTA / 4; k++) {
            const int row = o0 + k * 4 + slot;
            if (row >= total)
                __stcs(&ob[(size_t)row * D4_ + col], z);
        }
    }
}

extern "C" void kernel_launch(void* const* d_in, const int* in_sizes, int n_in,
                              void* d_out, int out_size) {
    const float* xs = (const float*)d_in[0];   // (16,1024,384) f32
    const int*   ds = (const int*)d_in[1];     // (16,1024) i32
    float* out = (float*)d_out;                // (16,4096,384) f32

    lr_fused_kernel<<<B_ * CTAS_PER_B, NTHREADS>>>(
        (const float4*)xs, ds, (float4*)out);
}

// round 13
// speedup vs baseline: 1.3616x; 1.3616x over previous
#include <cuda_runtime.h>
#include <cstdint>

// Problem constants (fixed by setup_inputs)
#define B_      16
#define T_      1024
#define D_      384
#define MAXDUR_ 4
#define OUTLEN_ (T_ * MAXDUR_)      // 4096
#define D4_     (D_ / 4)            // 96 float4 per row

#define G_THREADS    384            // gather CTA size
#define ROWS_PER_CTA 16             // 16 rows * 96 f4 = 1536 = 384 * 4
#define RPT          4              // rows per thread

#define S_THREADS    256            // scan CTA size (4 tokens/thread via int4)

// Scratch: per-output-frame source index, -1 => pad (zero fill)
__device__ int g_idx[B_ * OUTLEN_];

// ---------------------------------------------------------------------------
// Kernel 1 (slim): per-batch scan + index-table scatter.
// 16 CTAs x 256 threads. Each thread owns 4 consecutive tokens (one int4),
// does a warp scan over per-thread sums, warp 0 folds the 8 warp totals.
// Then each thread writes its 4 tokens' output slots and a pad-tail stride.
// ---------------------------------------------------------------------------
__global__ void __launch_bounds__(S_THREADS) scan_idx_kernel(const int* __restrict__ ds) {
    __shared__ int wsum[8];
    const int b    = blockIdx.x;
    const int tid  = threadIdx.x;
    const int lane = tid & 31;
    const int warp = tid >> 5;

    // 4 tokens per thread
    int4 dv = __ldg(&((const int4*)(ds + b * T_))[tid]);
    const int psum = dv.x + dv.y + dv.z + dv.w;

    // warp inclusive scan of per-thread sums
    int x = psum;
    #pragma unroll
    for (int off = 1; off < 32; off <<= 1) {
        int y = __shfl_up_sync(0xffffffffu, x, off);
        if (lane >= off) x += y;
    }
    if (lane == 31) wsum[warp] = x;
    __syncthreads();

    int total;
    {
        // every thread folds the 8 warp totals locally (cheap, no 2nd sync)
        int base = 0; total = 0;
        #pragma unroll
        for (int w = 0; w < 8; w++) {
            int t = wsum[w];
            if (w < warp) base += t;
            total += t;
        }
        x += base;               // inclusive cumsum through my 4 tokens
    }

    int* __restrict__ gi = &g_idx[b * OUTLEN_];

    // scatter: token (4*tid+j) covers [start_j, start_j + d_j)
    int start = x - psum;                 // exclusive prefix before my tokens
    const int tok0 = tid << 2;
    int dvs[4] = {dv.x, dv.y, dv.z, dv.w};
    #pragma unroll
    for (int j = 0; j < 4; j++) {
        const int d = dvs[j];
        for (int k = 0; k < d; k++) gi[start + k] = tok0 + j;
        start += d;
    }

    // pad tail: rows [total, 4096) get -1 (16 per thread max)
    for (int t = total + tid; t < OUTLEN_; t += S_THREADS) gi[t] = -1;
}

// ---------------------------------------------------------------------------
// Kernel 2: streaming gather — EXACT R2 config (best measured: 18.8us ncu,
// 21.0us harness). __ldg reads, MLP=4, __stcs stores.
// ---------------------------------------------------------------------------
__global__ void __launch_bounds__(G_THREADS) gather_kernel(
    const float4* __restrict__ xs, float4* __restrict__ out) {
    const int lr   = threadIdx.x / D4_;        // 0..3 local row within slice
    const int c    = threadIdx.x - lr * D4_;   // 0..95 column
    const int row0 = blockIdx.x * ROWS_PER_CTA;
    const int b    = row0 >> 12;               // same batch for whole CTA
    const float4* __restrict__ xb = xs + (size_t)b * T_ * D4_;

    // batch the 4 independent idx loads
    int idxs[RPT];
    #pragma unroll
    for (int k = 0; k < RPT; k++)
        idxs[k] = g_idx[row0 + k * 4 + lr];

    // batch the 4 independent gathers
    float4 v[RPT];
    #pragma unroll
    for (int k = 0; k < RPT; k++) {
        if (idxs[k] >= 0)
            v[k] = __ldg(&xb[(size_t)idxs[k] * D4_ + c]);
        else
            v[k] = make_float4(0.f, 0.f, 0.f, 0.f);
    }

    // streaming stores: keep 100MB of write-once data from squatting in L2
    #pragma unroll
    for (int k = 0; k < RPT; k++)
        __stcs(&out[(size_t)(row0 + k * 4 + lr) * D4_ + c], v[k]);
}

extern "C" void kernel_launch(void* const* d_in, const int* in_sizes, int n_in,
                              void* d_out, int out_size) {
    const float* xs = (const float*)d_in[0];   // (16,1024,384) f32
    const int*   ds = (const int*)d_in[1];     // (16,1024) i32
    float* out = (float*)d_out;                // (16,4096,384) f32

    scan_idx_kernel<<<B_, S_THREADS>>>(ds);
    gather_kernel<<<(B_ * OUTLEN_) / ROWS_PER_CTA, G_THREADS>>>(
        (const float4*)xs, (float4*)out);
}